// round 8
// baseline (speedup 1.0000x reference)
#include <cuda_runtime.h>
#include <cuda_fp16.h>
#include <cstdint>
#include <cmath>

// Problem constants
#define BB   128
#define LL   400
#define TT   30
#define EE   300
#define HE   512
#define HD   512
#define AA   512
#define VV   20000
#define PAD_ID 0
#define UNK_ID 1
#define SOS_ID 2

#define STAGES 4
#define SK     40                      // smem row stride in halfs (32 + 8 pad)
#define SMEM_GEMM (2 * STAGES * 64 * SK * 2)   // 40960 bytes
#define MGRID 128                      // persistent grid (<= SM count, co-resident)

// ---------------------------------------------------------------------------
// Scratch (device globals; distinct symbols only, all 256B aligned)
// ---------------------------------------------------------------------------
__device__ __align__(256) __half g_enc_h [(size_t)BB * LL * HE];     // 52 MB
__device__ __align__(256) __half g_proj_h[(size_t)BB * LL * AA];     // 52 MB
__device__ __align__(256) __half g_embed_h[(size_t)VV * 304];        // 12 MB
__device__ __align__(256) __half g_Wih_e[1536 * 304];
__device__ __align__(256) __half g_Wih_c[1536 * 512];
__device__ __align__(256) __half g_Whh  [1536 * 512];
__device__ __align__(256) __half g_Ws   [512 * 512];
__device__ __align__(256) __half g_Wh   [512 * 512];
__device__ __align__(256) __half g_Wr_e [512 * 304];
__device__ __align__(256) __half g_Wr_c [512 * 1024];
__device__ __align__(256) __half g_Wo   [(size_t)VV * 256];
__device__ __align__(256) float  g_giemb[(size_t)TT * BB * 1536];    // 23.6 MB
__device__ __align__(256) float  g_rvemb[(size_t)TT * BB * 512];     // 7.9 MB
__device__ __align__(256) float  g_gi   [BB * 1536];
__device__ __align__(256) float  g_gh   [BB * 1536];
__device__ __align__(256) float  g_qp   [4 * BB * 512];
// Per-step ring buffers
__device__ __align__(256) float  g_sf  [(size_t)(TT + 1) * BB * HD];
__device__ __align__(256) __half g_shh [(size_t)(TT + 1) * BB * HD];
__device__ __align__(256) __half g_chh [(size_t)(TT + 1) * BB * HE];
__device__ __align__(256) float  g_attnb[(size_t)TT * BB * LL];
__device__ __align__(256) float  g_pcb  [TT * BB];
// Batched tail buffers
__device__ __align__(256) float  g_rv_all [(size_t)TT * BB * 512];   // 7.9 MB
__device__ __align__(256) __half g_mh_all [(size_t)TT * BB * 256];   // 2 MB
__device__ __align__(256) float  g_energy_all[(size_t)TT * BB * VV]; // 307 MB
// Software grid barrier state (zero-initialized; self-resetting)
__device__ unsigned g_bar_cnt;
__device__ volatile unsigned g_bar_gen;

// ---------------------------------------------------------------------------
// Low-level helpers
// ---------------------------------------------------------------------------
__device__ __forceinline__ void cp_async16(uint32_t dst, const void* src, int bytes) {
    asm volatile("cp.async.ca.shared.global [%0], [%1], 16, %2;\n"
                 :: "r"(dst), "l"(src), "r"(bytes));
}
__device__ __forceinline__ void cp_commit() {
    asm volatile("cp.async.commit_group;\n" ::: "memory");
}
template <int N>
__device__ __forceinline__ void cp_wait() {
    asm volatile("cp.async.wait_group %0;\n" :: "n"(N) : "memory");
}

__device__ __forceinline__ void ldsm4(uint32_t (&r)[4], uint32_t addr) {
    asm volatile("ldmatrix.sync.aligned.m8n8.x4.shared.b16 {%0,%1,%2,%3}, [%4];"
                 : "=r"(r[0]), "=r"(r[1]), "=r"(r[2]), "=r"(r[3]) : "r"(addr));
}

__device__ __forceinline__ void mma_f16(float (&c)[4], const uint32_t (&a)[4],
                                        uint32_t b0, uint32_t b1) {
    asm volatile(
        "mma.sync.aligned.m16n8k16.row.col.f32.f16.f16.f32 "
        "{%0,%1,%2,%3}, {%4,%5,%6,%7}, {%8,%9}, {%0,%1,%2,%3};\n"
        : "+f"(c[0]), "+f"(c[1]), "+f"(c[2]), "+f"(c[3])
        : "r"(a[0]), "r"(a[1]), "r"(a[2]), "r"(a[3]), "r"(b0), "r"(b1));
}

__device__ __forceinline__ float tanhA(float x) {
    float y;
    asm("tanh.approx.f32 %0, %1;" : "=f"(y) : "f"(x));
    return y;
}
__device__ __forceinline__ float sigmoid_fast(float x) {
    return __fdividef(1.0f, 1.0f + __expf(-x));
}
__device__ __forceinline__ float tanh_fast(float x) {
    x = fminf(15.0f, fmaxf(-15.0f, x));
    float e = __expf(2.0f * x);
    return 1.0f - __fdividef(2.0f, e + 1.0f);
}

__device__ __forceinline__ float warpMax(float v) {
    #pragma unroll
    for (int o = 16; o; o >>= 1) v = fmaxf(v, __shfl_xor_sync(0xffffffffu, v, o));
    return v;
}
__device__ __forceinline__ float warpSum(float v) {
    #pragma unroll
    for (int o = 16; o; o >>= 1) v += __shfl_xor_sync(0xffffffffu, v, o);
    return v;
}
__device__ __forceinline__ float blockMax(float v, float* red) {
    v = warpMax(v);
    int w = threadIdx.x >> 5, l = threadIdx.x & 31, nw = blockDim.x >> 5;
    if (l == 0) red[w] = v;
    __syncthreads();
    if (threadIdx.x < 32) {
        float x = (threadIdx.x < nw) ? red[threadIdx.x] : -INFINITY;
        x = warpMax(x);
        if (threadIdx.x == 0) red[0] = x;
    }
    __syncthreads();
    v = red[0];
    __syncthreads();
    return v;
}
__device__ __forceinline__ float blockSum(float v, float* red) {
    v = warpSum(v);
    int w = threadIdx.x >> 5, l = threadIdx.x & 31, nw = blockDim.x >> 5;
    if (l == 0) red[w] = v;
    __syncthreads();
    if (threadIdx.x < 32) {
        float x = (threadIdx.x < nw) ? red[threadIdx.x] : 0.0f;
        x = warpSum(x);
        if (threadIdx.x == 0) red[0] = x;
    }
    __syncthreads();
    v = red[0];
    __syncthreads();
    return v;
}

// Software grid barrier: arrive (atomic) + spin on generation. Fences flush
// L1D (gpu-scope fence -> CCTL.IVALL on this arch) so cross-block data is safe.
__device__ __forceinline__ void gridbar() {
    __syncthreads();
    if (threadIdx.x == 0) {
        __threadfence();
        unsigned gen = g_bar_gen;
        if (atomicAdd(&g_bar_cnt, 1u) == (unsigned)(MGRID - 1)) {
            g_bar_cnt = 0;
            __threadfence();
            g_bar_gen = gen + 1;
        } else {
            while (g_bar_gen == gen) __nanosleep(32);
        }
        __threadfence();
    }
    __syncthreads();
}

// ---------------------------------------------------------------------------
// Convert/repack fp32 -> fp16 with optional column slice + zero padding
// ---------------------------------------------------------------------------
__global__ void cvt_pad(const float* __restrict__ src, __half* __restrict__ dst,
                        int rows, int sstr, int soff, int dstr, int clen)
{
    int total = rows * dstr;
    for (int i = blockIdx.x * blockDim.x + threadIdx.x; i < total;
         i += gridDim.x * blockDim.x) {
        int r = i / dstr, c = i - r * dstr;
        float v = (c < clen) ? src[(size_t)r * sstr + soff + c] : 0.0f;
        dst[i] = __float2half(v);
    }
}

// ---------------------------------------------------------------------------
// fp16 tensor-core GEMM tile: C[64,64] at (mt0,nt0) of C[M,N] = A[M,K]@W[N,K]^T
// 128 threads (4 warps 2x2, warp tile 32x32), K-chunk 32, 4-stage cp.async
// ---------------------------------------------------------------------------
struct GH {
    const __half* A; int lda;       // MODE_PLAIN
    const __half* W; int ldw;
    float* C; int ldc;
    int N;
    int kbeg, kend;                 // absolute K range
    const __half* embed;            // MODE_EMB
    const int*    tgt;
    const __half* ctx;              // MODE_CS
    const __half* s;
};

#define MODE_PLAIN 0
#define MODE_EMB   1   // A row m -> embed_h[word(t=m>>7, b=m&127)]
#define MODE_CS    2   // A = [ctx(512) | s(512)]

template <int MODE, bool OUTH>
__device__ __forceinline__ void grun_tile(const GH& g, int mt0, int nt0) {
    extern __shared__ __half smh[];
    __half* As = smh;
    __half* Ws = smh + STAGES * 64 * SK;

    const int tid = threadIdx.x, lane = tid & 31, warp = tid >> 5;
    const int wm = warp >> 1, wn = warp & 1;

    const int r0 = tid >> 2, kc = (tid & 3) * 8;
    const int r1 = r0 + 32;
    const int gm0 = mt0 + r0, gm1 = mt0 + r1;
    const int gn0 = nt0 + r0, gn1 = nt0 + r1;

    const __half *a0 = nullptr, *a1 = nullptr;
    const __half *c0p = nullptr, *c1p = nullptr, *s0p = nullptr, *s1p = nullptr;
    if (MODE == MODE_PLAIN) {
        a0 = g.A + (size_t)gm0 * g.lda;
        a1 = g.A + (size_t)gm1 * g.lda;
    } else if (MODE == MODE_EMB) {
        int t0 = gm0 >> 7, b0 = gm0 & 127;
        int w0 = (t0 == 0) ? SOS_ID : g.tgt[b0 * TT + t0 - 1];
        if (w0 >= VV) w0 = UNK_ID;
        int t1 = gm1 >> 7, b1 = gm1 & 127;
        int w1 = (t1 == 0) ? SOS_ID : g.tgt[b1 * TT + t1 - 1];
        if (w1 >= VV) w1 = UNK_ID;
        a0 = g.embed + (size_t)w0 * 304;
        a1 = g.embed + (size_t)w1 * 304;
    } else {
        c0p = g.ctx + (size_t)gm0 * 512; c1p = g.ctx + (size_t)gm1 * 512;
        s0p = g.s   + (size_t)gm0 * 512; s1p = g.s   + (size_t)gm1 * 512;
    }
    const bool n0ok = (gn0 < g.N), n1ok = (gn1 < g.N);
    const __half* w0p = g.W + (size_t)(n0ok ? gn0 : 0) * g.ldw;
    const __half* w1p = g.W + (size_t)(n1ok ? gn1 : 0) * g.ldw;

    const uint32_t asB = (uint32_t)__cvta_generic_to_shared(As);
    const uint32_t wsB = (uint32_t)__cvta_generic_to_shared(Ws);
    const int STB = 64 * SK * 2;
    const uint32_t aD0 = asB + (r0 * SK + kc) * 2;
    const uint32_t aD1 = asB + (r1 * SK + kc) * 2;
    const uint32_t wD0 = wsB + (r0 * SK + kc) * 2;
    const uint32_t wD1 = wsB + (r1 * SK + kc) * 2;

    const int nk = (g.kend - g.kbeg + 31) >> 5;

    auto pf = [&](int i) {
        int kg = g.kbeg + i * 32 + kc;
        int buf = (i & 3) * STB;
        bool v = kg < g.kend;
        const __half *sa0, *sa1;
        if (MODE == MODE_CS) {
            sa0 = (kg < 512) ? c0p + kg : s0p + (kg - 512);
            sa1 = (kg < 512) ? c1p + kg : s1p + (kg - 512);
        } else {
            sa0 = a0 + kg; sa1 = a1 + kg;
        }
        if (!v) { sa0 = g.W; sa1 = g.W; }
        cp_async16(aD0 + buf, sa0, v ? 16 : 0);
        cp_async16(aD1 + buf, sa1, v ? 16 : 0);
        bool v0 = v && n0ok, v1 = v && n1ok;
        cp_async16(wD0 + buf, v0 ? (w0p + kg) : g.W, v0 ? 16 : 0);
        cp_async16(wD1 + buf, v1 ? (w1p + kg) : g.W, v1 ? 16 : 0);
    };

    #pragma unroll
    for (int p = 0; p < 3; p++) {
        if (p < nk) pf(p);
        cp_commit();
    }

    float c[2][4][4] = {};
    const int lr = lane & 15, lk = (lane >> 4) * 8;

    for (int i = 0; i < nk; i++) {
        if (i + 3 < nk) pf(i + 3);
        cp_commit();
        cp_wait<3>();
        __syncthreads();

        const uint32_t ab = asB + (i & 3) * STB;
        const uint32_t wb = wsB + (i & 3) * STB;

        #pragma unroll
        for (int kk = 0; kk < 32; kk += 16) {
            uint32_t a[2][4], bb[2][4];
            #pragma unroll
            for (int mt = 0; mt < 2; mt++)
                ldsm4(a[mt], ab + ((wm * 32 + mt * 16 + lr) * SK + kk + lk) * 2);
            #pragma unroll
            for (int n2 = 0; n2 < 2; n2++)
                ldsm4(bb[n2], wb + ((wn * 32 + n2 * 16 + lr) * SK + kk + lk) * 2);
            #pragma unroll
            for (int mt = 0; mt < 2; mt++)
                #pragma unroll
                for (int ns = 0; ns < 4; ns++) {
                    int n2 = ns >> 1, sel = ns & 1;
                    mma_f16(c[mt][ns], a[mt], bb[n2][sel], bb[n2][sel + 2]);
                }
        }
        __syncthreads();
    }

    const int gr = lane >> 2, gc = (lane & 3) * 2;
    #pragma unroll
    for (int mt = 0; mt < 2; mt++)
        #pragma unroll
        for (int ns = 0; ns < 4; ns++) {
            int row = mt0 + wm * 32 + mt * 16 + gr;
            int col = nt0 + wn * 32 + ns * 8 + gc;
            if (col < g.N) {
                if (OUTH) {
                    __half* Ch = (__half*)g.C;
                    Ch[(size_t)row * g.ldc + col]           = __float2half(c[mt][ns][0]);
                    Ch[(size_t)row * g.ldc + col + 1]       = __float2half(c[mt][ns][1]);
                    Ch[(size_t)(row + 8) * g.ldc + col]     = __float2half(c[mt][ns][2]);
                    Ch[(size_t)(row + 8) * g.ldc + col + 1] = __float2half(c[mt][ns][3]);
                } else {
                    g.C[(size_t)row * g.ldc + col]           = c[mt][ns][0];
                    g.C[(size_t)row * g.ldc + col + 1]       = c[mt][ns][1];
                    g.C[(size_t)(row + 8) * g.ldc + col]     = c[mt][ns][2];
                    g.C[(size_t)(row + 8) * g.ldc + col + 1] = c[mt][ns][3];
                }
            }
        }
}

// Wrapper kernels (precompute + tail)
__global__ __launch_bounds__(128) void k_g_plain(GH g) {
    grun_tile<MODE_PLAIN, false>(g, blockIdx.y * 64, blockIdx.x * 64);
}
__global__ __launch_bounds__(128) void k_g_plain_h(GH g) {
    grun_tile<MODE_PLAIN, true>(g, blockIdx.y * 64, blockIdx.x * 64);
}
__global__ __launch_bounds__(128) void k_g_emb(GH g) {
    grun_tile<MODE_EMB, false>(g, blockIdx.y * 64, blockIdx.x * 64);
}
__global__ __launch_bounds__(128) void k_g_cs(GH g) {
    grun_tile<MODE_CS, false>(g, blockIdx.y * 64, blockIdx.x * 64);
}

// ---------------------------------------------------------------------------
// Attention row (128 threads): q-assemble -> scores -> softmax -> ctx -> p_copy
// ---------------------------------------------------------------------------
__device__ void attn_row(
    int b, const float* __restrict__ qp, const float* __restrict__ att_b,
    const __half* __restrict__ proj, const __half* __restrict__ ench,
    const float* __restrict__ vvec, const int* __restrict__ src,
    const float* __restrict__ sN, const float* __restrict__ copy_W,
    const float* __restrict__ copy_b,
    float* __restrict__ atT, __half* __restrict__ chN, float* __restrict__ pcT)
{
    extern __shared__ float smf[];
    float* qs = smf;            // [512]
    float* es = smf + 512;      // [400]
    __shared__ float red[32];

    int tid = threadIdx.x, lane = tid & 31, warp = tid >> 5;

    // q = bias + sum of 4 split-K partials
    for (int a = tid; a < AA; a += 128) {
        float v = att_b[a];
        #pragma unroll
        for (int sp = 0; sp < 4; sp++) v += qp[((size_t)sp * BB + b) * 512 + a];
        qs[a] = v;
    }
    __syncthreads();

    // lane-register layout matching uint4 proj reads
    float qf[2][8], vf[2][8];
    #pragma unroll
    for (int j = 0; j < 2; j++)
        #pragma unroll
        for (int p = 0; p < 8; p++) {
            qf[j][p] = qs[j * 256 + lane * 8 + p];
            vf[j][p] = vvec[j * 256 + lane * 8 + p];
        }

    // scores (4 warps, 100 l each)
    for (int l = warp; l < LL; l += 4) {
        const uint4* pp = (const uint4*)(proj + ((size_t)b * LL + l) * AA);
        float acc = 0.0f;
        #pragma unroll
        for (int j = 0; j < 2; j++) {
            uint4 pv = pp[j * 32 + lane];
            const __half2* h2 = (const __half2*)&pv;
            #pragma unroll
            for (int p = 0; p < 4; p++) {
                float2 f = __half22float2(h2[p]);
                acc += tanhA(f.x + qf[j][2 * p])     * vf[j][2 * p];
                acc += tanhA(f.y + qf[j][2 * p + 1]) * vf[j][2 * p + 1];
            }
        }
        acc = warpSum(acc);
        if (lane == 0)
            es[l] = (src[b * LL + l] == PAD_ID) ? -1e30f : acc;
    }
    __syncthreads();

    // softmax over L
    float mx = -INFINITY;
    for (int l = tid; l < LL; l += 128) mx = fmaxf(mx, es[l]);
    mx = blockMax(mx, red);
    float sm = 0.0f;
    for (int l = tid; l < LL; l += 128) {
        float p = __expf(es[l] - mx);
        es[l] = p;
        sm += p;
    }
    sm = blockSum(sm, red);
    float inv = __fdividef(1.0f, sm);
    for (int l = tid; l < LL; l += 128) {
        float a = es[l] * inv;
        es[l] = a;
        atT[b * LL + l] = a;
    }
    __syncthreads();

    // ctx: thread owns 4 consecutive columns (2 half2)
    const __half2* eb = (const __half2*)(ench + (size_t)b * LL * HE);
    int c2 = tid * 2;
    float a0 = 0, a1 = 0, a2 = 0, a3 = 0;
    #pragma unroll 4
    for (int l = 0; l < LL; l++) {
        float w = es[l];
        float2 f0 = __half22float2(eb[l * 256 + c2]);
        float2 f1 = __half22float2(eb[l * 256 + c2 + 1]);
        a0 += w * f0.x; a1 += w * f0.y; a2 += w * f1.x; a3 += w * f1.y;
    }
    int c = tid * 4;
    __half2* co = (__half2*)(chN + b * HE + c);
    co[0] = __floats2half2_rn(a0, a1);
    co[1] = __floats2half2_rn(a2, a3);

    // p_copy
    const float* sb = sN + b * HD;
    float pp_ = sb[c] * copy_W[c] + sb[c + 1] * copy_W[c + 1]
              + sb[c + 2] * copy_W[c + 2] + sb[c + 3] * copy_W[c + 3]
              + a0 * copy_W[HD + c] + a1 * copy_W[HD + c + 1]
              + a2 * copy_W[HD + c + 2] + a3 * copy_W[HD + c + 3];
    float tot = blockSum(pp_, red);
    if (tid == 0) pcT[b] = sigmoid_fast(tot + copy_b[0]);
}

// ---------------------------------------------------------------------------
// Persistent megakernel: the entire 30-step recurrence, 4 grid-bars per step
// ---------------------------------------------------------------------------
__global__ __launch_bounds__(128) void mega(
    const __half* __restrict__ Wihc, const __half* __restrict__ Whh,
    const __half* __restrict__ Ws,
    const float* __restrict__ giemb,
    const float* __restrict__ b_ih, const float* __restrict__ b_hh,
    float* __restrict__ gi, float* __restrict__ gh, float* __restrict__ qp,
    float* __restrict__ sf, __half* __restrict__ shh, __half* __restrict__ chh,
    const __half* __restrict__ proj, const __half* __restrict__ ench,
    const float* __restrict__ att_b, const float* __restrict__ att_v,
    const int* __restrict__ src,
    const float* __restrict__ copy_W, const float* __restrict__ copy_b,
    float* __restrict__ attnb, float* __restrict__ pcb)
{
    const int bid = blockIdx.x, tid = threadIdx.x;

    for (int t = 0; t < TT; t++) {
        const __half* shC = shh + (size_t)t * BB * HD;
        __half*       shN = shh + (size_t)(t + 1) * BB * HD;
        const __half* chC = chh + (size_t)t * BB * HE;
        __half*       chN = chh + (size_t)(t + 1) * BB * HE;
        const float*  sCur = sf + (size_t)t * BB * HD;
        float*        sNxt = sf + (size_t)(t + 1) * BB * HD;

        // Phase A: gates GEMMs (gi: ctx@Wihc, gh: s@Whh), 96 tile jobs
        {
            GH gia{}; gia.A = chC; gia.lda = 512; gia.W = Wihc; gia.ldw = 512;
            gia.C = gi; gia.ldc = 1536; gia.N = 1536; gia.kbeg = 0; gia.kend = 512;
            GH gha{}; gha.A = shC; gha.lda = 512; gha.W = Whh; gha.ldw = 512;
            gha.C = gh; gha.ldc = 1536; gha.N = 1536; gha.kbeg = 0; gha.kend = 512;
            for (int job = bid; job < 96; job += MGRID) {
                int j = job < 48 ? job : job - 48;
                int mt0 = (j / 24) * 64, nt0 = (j % 24) * 64;
                if (job < 48) grun_tile<MODE_PLAIN, false>(gia, mt0, nt0);
                else          grun_tile<MODE_PLAIN, false>(gha, mt0, nt0);
            }
        }
        gridbar();

        // Phase B: GRU elementwise
        for (int i = bid * 128 + tid; i < BB * HD; i += MGRID * 128) {
            int b = i >> 9, h = i & 511;
            size_t ob = (size_t)b * 1536;
            size_t oe = ((size_t)t * BB + b) * 1536;
            float ir = gi[ob + h]        + giemb[oe + h]        + b_ih[h];
            float iz = gi[ob + 512 + h]  + giemb[oe + 512 + h]  + b_ih[512 + h];
            float in = gi[ob + 1024 + h] + giemb[oe + 1024 + h] + b_ih[1024 + h];
            float hr = gh[ob + h]        + b_hh[h];
            float hz = gh[ob + 512 + h]  + b_hh[512 + h];
            float hn = gh[ob + 1024 + h] + b_hh[1024 + h];
            float r = sigmoid_fast(ir + hr);
            float z = sigmoid_fast(iz + hz);
            float n = tanh_fast(in + r * hn);
            float sn = (1.0f - z) * n + z * sCur[i];
            sNxt[i] = sn;
            shN[i] = __float2half(sn);
        }
        gridbar();

        // Phase C: q partials = s_new @ att_Ws^T, splitK4 x 16 tiles
        {
            GH qa{}; qa.A = shN; qa.lda = 512; qa.W = Ws; qa.ldw = 512;
            qa.ldc = 512; qa.N = 512;
            for (int job = bid; job < 64; job += MGRID) {
                int sp = job >> 4, tile = job & 15;
                GH g2 = qa;
                g2.kbeg = sp * 128; g2.kend = sp * 128 + 128;
                g2.C = qp + (size_t)sp * BB * 512;
                grun_tile<MODE_PLAIN, false>(g2, (tile >> 3) * 64, (tile & 7) * 64);
            }
        }
        gridbar();

        // Phase D: attention (one block per batch row)
        if (bid < BB)
            attn_row(bid, qp, att_b, proj, ench, att_v, src, sNxt,
                     copy_W, copy_b,
                     attnb + (size_t)t * BB * LL, chN, pcb + (size_t)t * BB);
        gridbar();
    }
}

// ---------------------------------------------------------------------------
// Batched tail over all 30 steps
// ---------------------------------------------------------------------------
__global__ __launch_bounds__(256) void mred_all(
    const float* __restrict__ rv, const float* __restrict__ rvemb,
    const float* __restrict__ read_b, __half* __restrict__ mh)
{
    int idx = blockIdx.x * 256 + threadIdx.x;     // TT*BB*256
    int row = idx >> 8, c = idx & 255;
    size_t o = (size_t)row * 512;
    float r0 = rv[o + 2 * c]     + rvemb[o + 2 * c]     + read_b[2 * c];
    float r1 = rv[o + 2 * c + 1] + rvemb[o + 2 * c + 1] + read_b[2 * c + 1];
    mh[idx] = __float2half(fmaxf(r0, r1));
}

__global__ __launch_bounds__(1024) void output_all(
    const float* __restrict__ energy,
    const float* __restrict__ attnb,
    const float* __restrict__ pcb,
    float* __restrict__ out)
{
    __shared__ float red[32];
    int row = blockIdx.x;                 // t*128 + b
    int t = row >> 7, b = row & 127;
    int tid = threadIdx.x;
    const float4* eb4 = (const float4*)(energy + (size_t)row * VV);

    float mx = -INFINITY;
    for (int j = tid; j < VV / 4; j += 1024) {
        float4 v = eb4[j];
        mx = fmaxf(mx, fmaxf(fmaxf(v.x, v.y), fmaxf(v.z, v.w)));
    }
    mx = blockMax(mx, red);

    float sm = 0.0f;
    for (int j = tid; j < VV / 4; j += 1024) {
        float4 v = eb4[j];
        sm += __expf(v.x - mx) + __expf(v.y - mx) + __expf(v.z - mx) + __expf(v.w - mx);
    }
    sm = blockSum(sm, red);

    float pc = pcb[(size_t)t * BB + b];
    float scale = (1.0f - pc) / sm;
    float* ob = out + ((size_t)b * TT + t) * (VV + LL);
    float4* ob4 = (float4*)ob;
    for (int j = tid; j < VV / 4; j += 1024) {
        float4 v = eb4[j], o;
        o.x = __logf(__expf(v.x - mx) * scale + 1e-12f);
        o.y = __logf(__expf(v.y - mx) * scale + 1e-12f);
        o.z = __logf(__expf(v.z - mx) * scale + 1e-12f);
        o.w = __logf(__expf(v.w - mx) * scale + 1e-12f);
        ob4[j] = o;
    }
    const float4* at4 = (const float4*)(attnb + ((size_t)t * BB + b) * LL);
    float4* oc4 = (float4*)(ob + VV);
    for (int j = tid; j < LL / 4; j += 1024) {
        float4 a = at4[j], o;
        o.x = __logf(fmaf(pc, a.x, 1e-12f));
        o.y = __logf(fmaf(pc, a.y, 1e-12f));
        o.z = __logf(fmaf(pc, a.z, 1e-12f));
        o.w = __logf(fmaf(pc, a.w, 1e-12f));
        oc4[j] = o;
    }
}

// ---------------------------------------------------------------------------
// Host orchestration: precompute -> mega (1 launch) -> batched tail (4 launches)
// ---------------------------------------------------------------------------
static inline void cvt(const float* s, __half* d, int rows, int sstr, int soff,
                       int dstr, int clen) {
    int total = rows * dstr;
    int grid = (total + 255) / 256;
    if (grid > 8192) grid = 8192;
    cvt_pad<<<grid, 256>>>(s, d, rows, sstr, soff, dstr, clen);
}

extern "C" void kernel_launch(void* const* d_in, const int* in_sizes, int n_in,
                              void* d_out, int out_size)
{
    const float* enc     = (const float*)d_in[0];
    const float* s_in    = (const float*)d_in[1];
    const int*   src     = (const int*)  d_in[2];
    const int*   tgt     = (const int*)  d_in[3];
    const float* embed   = (const float*)d_in[4];
    const float* W_ih    = (const float*)d_in[5];
    const float* b_ih    = (const float*)d_in[6];
    const float* W_hh    = (const float*)d_in[7];
    const float* b_hh    = (const float*)d_in[8];
    const float* att_Wh  = (const float*)d_in[9];
    const float* att_Ws  = (const float*)d_in[10];
    const float* att_b   = (const float*)d_in[11];
    const float* att_v   = (const float*)d_in[12];
    const float* copy_W  = (const float*)d_in[13];
    const float* copy_b  = (const float*)d_in[14];
    const float* read_W  = (const float*)d_in[15];
    const float* read_b  = (const float*)d_in[16];
    const float* read_Wo = (const float*)d_in[17];
    float* out = (float*)d_out;

    __half *p_ench, *p_projh, *p_embh, *p_Wihe, *p_Wihc, *p_Whh, *p_Ws, *p_Wh;
    __half *p_Wre, *p_Wrc, *p_Wo, *p_shh, *p_chh, *p_mh;
    float *p_giemb, *p_rvemb, *p_gi, *p_gh, *p_qp, *p_rv;
    float *p_sf, *p_attn, *p_pc, *p_energy;

    cudaGetSymbolAddress((void**)&p_ench,  g_enc_h);
    cudaGetSymbolAddress((void**)&p_projh, g_proj_h);
    cudaGetSymbolAddress((void**)&p_embh,  g_embed_h);
    cudaGetSymbolAddress((void**)&p_Wihe,  g_Wih_e);
    cudaGetSymbolAddress((void**)&p_Wihc,  g_Wih_c);
    cudaGetSymbolAddress((void**)&p_Whh,   g_Whh);
    cudaGetSymbolAddress((void**)&p_Ws,    g_Ws);
    cudaGetSymbolAddress((void**)&p_Wh,    g_Wh);
    cudaGetSymbolAddress((void**)&p_Wre,   g_Wr_e);
    cudaGetSymbolAddress((void**)&p_Wrc,   g_Wr_c);
    cudaGetSymbolAddress((void**)&p_Wo,    g_Wo);
    cudaGetSymbolAddress((void**)&p_giemb, g_giemb);
    cudaGetSymbolAddress((void**)&p_rvemb, g_rvemb);
    cudaGetSymbolAddress((void**)&p_gi,    g_gi);
    cudaGetSymbolAddress((void**)&p_gh,    g_gh);
    cudaGetSymbolAddress((void**)&p_qp,    g_qp);
    cudaGetSymbolAddress((void**)&p_sf,    g_sf);
    cudaGetSymbolAddress((void**)&p_shh,   g_shh);
    cudaGetSymbolAddress((void**)&p_chh,   g_chh);
    cudaGetSymbolAddress((void**)&p_attn,  g_attnb);
    cudaGetSymbolAddress((void**)&p_pc,    g_pcb);
    cudaGetSymbolAddress((void**)&p_rv,    g_rv_all);
    cudaGetSymbolAddress((void**)&p_mh,    g_mh_all);
    cudaGetSymbolAddress((void**)&p_energy,g_energy_all);

    // ---- Precompute: conversions / repacks ----
    cvt(enc,     p_ench, BB * LL, HE, 0, HE, HE);
    cvt(embed,   p_embh, VV, EE, 0, 304, EE);
    cvt(W_ih,    p_Wihe, 1536, 812, 0, 304, 300);
    cvt(W_ih,    p_Wihc, 1536, 812, 300, 512, 512);
    cvt(W_hh,    p_Whh,  1536, 512, 0, 512, 512);
    cvt(att_Ws,  p_Ws,   512, 512, 0, 512, 512);
    cvt(att_Wh,  p_Wh,   512, 512, 0, 512, 512);
    cvt(read_W,  p_Wre,  512, 1324, 0, 304, 300);
    cvt(read_W,  p_Wrc,  512, 1324, 300, 1024, 1024);
    cvt(read_Wo, p_Wo,   VV, 256, 0, 256, 256);
    cvt(s_in,    p_shh,  BB, HD, 0, HD, HD);     // s ring slot 0

    cudaMemcpyAsync(p_sf, s_in, BB * HD * sizeof(float),
                    cudaMemcpyDeviceToDevice, 0);
    cudaMemsetAsync(p_chh, 0, BB * HE * sizeof(__half), 0);   // ctx slot 0

    // ---- Precompute: big GEMMs ----
    {   // proj = enc @ att_Wh^T -> fp16
        GH g{}; g.A = p_ench; g.lda = HE; g.W = p_Wh; g.ldw = 512;
        g.C = (float*)p_projh; g.ldc = AA; g.N = AA;
        g.kbeg = 0; g.kend = 512;
        k_g_plain_h<<<dim3(8, 800), 128, SMEM_GEMM>>>(g);
    }
    {   // giemb[all t] = emb @ Wih_e^T
        GH g{}; g.embed = p_embh; g.tgt = tgt; g.W = p_Wihe; g.ldw = 304;
        g.C = p_giemb; g.ldc = 1536; g.N = 1536;
        g.kbeg = 0; g.kend = 304;
        k_g_emb<<<dim3(24, 60), 128, SMEM_GEMM>>>(g);
    }
    {   // rvemb[all t] = emb @ Wr_e^T
        GH g{}; g.embed = p_embh; g.tgt = tgt; g.W = p_Wre; g.ldw = 304;
        g.C = p_rvemb; g.ldc = 512; g.N = 512;
        g.kbeg = 0; g.kend = 304;
        k_g_emb<<<dim3(8, 60), 128, SMEM_GEMM>>>(g);
    }

    // ---- Persistent recurrence: ONE launch ----
    mega<<<MGRID, 128, SMEM_GEMM>>>(
        p_Wihc, p_Whh, p_Ws, p_giemb, b_ih, b_hh,
        p_gi, p_gh, p_qp, p_sf, p_shh, p_chh,
        p_projh, p_ench, att_b, att_v, src, copy_W, copy_b,
        p_attn, p_pc);

    // ---- Batched tail over all 30 steps ----
    {   // rv_all = [ctx(t+1), s(t+1)] @ Wr_c^T,  M = 30*128
        GH g{}; g.ctx = p_chh + BB * HE; g.s = p_shh + BB * HD;
        g.W = p_Wrc; g.ldw = 1024;
        g.C = p_rv; g.ldc = 512; g.N = 512;
        g.kbeg = 0; g.kend = 1024;
        k_g_cs<<<dim3(8, 60), 128, SMEM_GEMM>>>(g);
    }
    mred_all<<<(TT * BB * 256) / 256, 256>>>(p_rv, p_rvemb, read_b, p_mh);
    {   // energy_all = m @ read_Wo^T,  M = 3840, N = 20000
        GH g{}; g.A = p_mh; g.lda = 256; g.W = p_Wo; g.ldw = 256;
        g.C = p_energy; g.ldc = VV; g.N = VV;
        g.kbeg = 0; g.kend = 256;
        k_g_plain<<<dim3(313, 60), 128, SMEM_GEMM>>>(g);
    }
    output_all<<<TT * BB, 1024>>>(p_energy, p_attn, p_pc, out);
}

// round 9
// speedup vs baseline: 1.8565x; 1.8565x over previous
#include <cuda_runtime.h>
#include <cuda_fp16.h>
#include <cstdint>
#include <cmath>

// Problem constants
#define BB   128
#define LL   400
#define TT   30
#define EE   300
#define HE   512
#define HD   512
#define AA   512
#define VV   20000
#define PAD_ID 0
#define UNK_ID 1
#define SOS_ID 2

#define STAGES 4
#define SK     40                      // smem row stride in halfs (32 + 8 pad)
#define SMEM_GEMM (2 * STAGES * 64 * SK * 2)   // 40960 bytes
#define CHUNK 10                       // tail batch size (steps)

// ---------------------------------------------------------------------------
// Scratch (device globals; distinct symbols only, all 256B aligned)
// ---------------------------------------------------------------------------
__device__ __align__(256) __half g_enc_h [(size_t)BB * LL * HE];     // 52 MB
__device__ __align__(256) __half g_proj_h[(size_t)BB * LL * AA];     // 52 MB
__device__ __align__(256) __half g_embed_h[(size_t)VV * 304];        // 12 MB
__device__ __align__(256) __half g_Wih_e[1536 * 304];
__device__ __align__(256) __half g_Wih_c[1536 * 512];
__device__ __align__(256) __half g_Whh  [1536 * 512];
__device__ __align__(256) __half g_Ws   [512 * 512];
__device__ __align__(256) __half g_Wh   [512 * 512];
__device__ __align__(256) __half g_Wr_e [512 * 304];
__device__ __align__(256) __half g_Wr_c [512 * 1024];
__device__ __align__(256) __half g_Wo   [(size_t)VV * 256];
__device__ __align__(256) float  g_giemb[(size_t)TT * BB * 1536];    // 23.6 MB
__device__ __align__(256) float  g_rvemb[(size_t)TT * BB * 512];     // 7.9 MB
__device__ __align__(256) float  g_gi_p [4 * BB * 1536];
__device__ __align__(256) float  g_gh_p [4 * BB * 1536];
__device__ __align__(256) float  g_qp   [4 * BB * 512];
// Per-step ring buffers
__device__ __align__(256) float  g_sf  [(size_t)(TT + 1) * BB * HD];
__device__ __align__(256) __half g_shh [(size_t)(TT + 1) * BB * HD];
__device__ __align__(256) __half g_chh [(size_t)(TT + 1) * BB * HE];
__device__ __align__(256) float  g_attnb[(size_t)TT * BB * LL];
__device__ __align__(256) float  g_pcb  [TT * BB];
// Batched tail buffers
__device__ __align__(256) float  g_rv_all [(size_t)TT * BB * 512];   // 7.9 MB
__device__ __align__(256) __half g_mh_all [(size_t)TT * BB * 256];   // 2 MB
__device__ __align__(256) float  g_energy_all[(size_t)TT * BB * VV]; // 307 MB

// ---------------------------------------------------------------------------
// Low-level helpers
// ---------------------------------------------------------------------------
__device__ __forceinline__ void cp_async16(uint32_t dst, const void* src, int bytes) {
    asm volatile("cp.async.ca.shared.global [%0], [%1], 16, %2;\n"
                 :: "r"(dst), "l"(src), "r"(bytes));
}
__device__ __forceinline__ void cp_commit() {
    asm volatile("cp.async.commit_group;\n" ::: "memory");
}
template <int N>
__device__ __forceinline__ void cp_wait() {
    asm volatile("cp.async.wait_group %0;\n" :: "n"(N) : "memory");
}

__device__ __forceinline__ void ldsm4(uint32_t (&r)[4], uint32_t addr) {
    asm volatile("ldmatrix.sync.aligned.m8n8.x4.shared.b16 {%0,%1,%2,%3}, [%4];"
                 : "=r"(r[0]), "=r"(r[1]), "=r"(r[2]), "=r"(r[3]) : "r"(addr));
}

__device__ __forceinline__ void mma_f16(float (&c)[4], const uint32_t (&a)[4],
                                        uint32_t b0, uint32_t b1) {
    asm volatile(
        "mma.sync.aligned.m16n8k16.row.col.f32.f16.f16.f32 "
        "{%0,%1,%2,%3}, {%4,%5,%6,%7}, {%8,%9}, {%0,%1,%2,%3};\n"
        : "+f"(c[0]), "+f"(c[1]), "+f"(c[2]), "+f"(c[3])
        : "r"(a[0]), "r"(a[1]), "r"(a[2]), "r"(a[3]), "r"(b0), "r"(b1));
}

__device__ __forceinline__ float tanhA(float x) {
    float y;
    asm("tanh.approx.f32 %0, %1;" : "=f"(y) : "f"(x));
    return y;
}
__device__ __forceinline__ float sigmoid_fast(float x) {
    return __fdividef(1.0f, 1.0f + __expf(-x));
}
__device__ __forceinline__ float tanh_fast(float x) {
    x = fminf(15.0f, fmaxf(-15.0f, x));
    float e = __expf(2.0f * x);
    return 1.0f - __fdividef(2.0f, e + 1.0f);
}

__device__ __forceinline__ float warpMax(float v) {
    #pragma unroll
    for (int o = 16; o; o >>= 1) v = fmaxf(v, __shfl_xor_sync(0xffffffffu, v, o));
    return v;
}
__device__ __forceinline__ float warpSum(float v) {
    #pragma unroll
    for (int o = 16; o; o >>= 1) v += __shfl_xor_sync(0xffffffffu, v, o);
    return v;
}
__device__ __forceinline__ float blockMax(float v, float* red) {
    v = warpMax(v);
    int w = threadIdx.x >> 5, l = threadIdx.x & 31, nw = blockDim.x >> 5;
    if (l == 0) red[w] = v;
    __syncthreads();
    if (threadIdx.x < 32) {
        float x = (threadIdx.x < nw) ? red[threadIdx.x] : -INFINITY;
        x = warpMax(x);
        if (threadIdx.x == 0) red[0] = x;
    }
    __syncthreads();
    v = red[0];
    __syncthreads();
    return v;
}
__device__ __forceinline__ float blockSum(float v, float* red) {
    v = warpSum(v);
    int w = threadIdx.x >> 5, l = threadIdx.x & 31, nw = blockDim.x >> 5;
    if (l == 0) red[w] = v;
    __syncthreads();
    if (threadIdx.x < 32) {
        float x = (threadIdx.x < nw) ? red[threadIdx.x] : 0.0f;
        x = warpSum(x);
        if (threadIdx.x == 0) red[0] = x;
    }
    __syncthreads();
    v = red[0];
    __syncthreads();
    return v;
}

// ---------------------------------------------------------------------------
// Convert/repack fp32 -> fp16 with optional column slice + zero padding
// ---------------------------------------------------------------------------
__global__ void cvt_pad(const float* __restrict__ src, __half* __restrict__ dst,
                        int rows, int sstr, int soff, int dstr, int clen)
{
    int total = rows * dstr;
    for (int i = blockIdx.x * blockDim.x + threadIdx.x; i < total;
         i += gridDim.x * blockDim.x) {
        int r = i / dstr, c = i - r * dstr;
        float v = (c < clen) ? src[(size_t)r * sstr + soff + c] : 0.0f;
        dst[i] = __float2half(v);
    }
}

// ---------------------------------------------------------------------------
// fp16 tensor-core GEMM: C[M,N] = A[M,K] @ W[N,K]^T
// block tile 64x64, K-chunk 32, 128 threads (4 warps, 2x2, warp tile 32x32)
// ---------------------------------------------------------------------------
struct GH {
    const __half* A; int lda;       // MODE_PLAIN
    const __half* W; int ldw;
    float* C; int ldc;
    int N;
    int K;                          // K per split (multiple of 32)
    int kbeg, kend;                 // absolute column range [kbeg, kend)
    const __half* embed;            // MODE_EMB
    const int*    tgt;
    const __half* ctx;              // MODE_CS
    const __half* s;
};

#define MODE_PLAIN 0
#define MODE_EMB   1   // A row m -> embed_h[word(t=m>>7, b=m&127)]
#define MODE_CS    2   // A = [ctx(512) | s(512)]

template <int MODE, bool OUTH>
__device__ __forceinline__ void grun(const GH& g) {
    extern __shared__ __half smh[];
    __half* As = smh;
    __half* Ws = smh + STAGES * 64 * SK;

    const int tid = threadIdx.x, lane = tid & 31, warp = tid >> 5;
    const int wm = warp >> 1, wn = warp & 1;
    const int mt0 = blockIdx.y * 64, nt0 = blockIdx.x * 64;

    const int r0 = tid >> 2, kc = (tid & 3) * 8;
    const int r1 = r0 + 32;
    const int gm0 = mt0 + r0, gm1 = mt0 + r1;
    const int gn0 = nt0 + r0, gn1 = nt0 + r1;

    const __half *a0 = nullptr, *a1 = nullptr;
    const __half *c0p = nullptr, *c1p = nullptr, *s0p = nullptr, *s1p = nullptr;
    if (MODE == MODE_PLAIN) {
        a0 = g.A + (size_t)gm0 * g.lda;
        a1 = g.A + (size_t)gm1 * g.lda;
    } else if (MODE == MODE_EMB) {
        int t0 = gm0 >> 7, b0 = gm0 & 127;
        int w0 = (t0 == 0) ? SOS_ID : g.tgt[b0 * TT + t0 - 1];
        if (w0 >= VV) w0 = UNK_ID;
        int t1 = gm1 >> 7, b1 = gm1 & 127;
        int w1 = (t1 == 0) ? SOS_ID : g.tgt[b1 * TT + t1 - 1];
        if (w1 >= VV) w1 = UNK_ID;
        a0 = g.embed + (size_t)w0 * 304;
        a1 = g.embed + (size_t)w1 * 304;
    } else {
        c0p = g.ctx + (size_t)gm0 * 512; c1p = g.ctx + (size_t)gm1 * 512;
        s0p = g.s   + (size_t)gm0 * 512; s1p = g.s   + (size_t)gm1 * 512;
    }
    const bool n0ok = (gn0 < g.N), n1ok = (gn1 < g.N);
    const __half* w0p = g.W + (size_t)(n0ok ? gn0 : 0) * g.ldw;
    const __half* w1p = g.W + (size_t)(n1ok ? gn1 : 0) * g.ldw;

    const uint32_t asB = (uint32_t)__cvta_generic_to_shared(As);
    const uint32_t wsB = (uint32_t)__cvta_generic_to_shared(Ws);
    const int STB = 64 * SK * 2;
    const uint32_t aD0 = asB + (r0 * SK + kc) * 2;
    const uint32_t aD1 = asB + (r1 * SK + kc) * 2;
    const uint32_t wD0 = wsB + (r0 * SK + kc) * 2;
    const uint32_t wD1 = wsB + (r1 * SK + kc) * 2;

    const int nk = (g.kend - g.kbeg + 31) >> 5;

    auto pf = [&](int i) {
        int kg = g.kbeg + i * 32 + kc;
        int buf = (i & 3) * STB;
        bool v = kg < g.kend;
        const __half *sa0, *sa1;
        if (MODE == MODE_CS) {
            sa0 = (kg < 512) ? c0p + kg : s0p + (kg - 512);
            sa1 = (kg < 512) ? c1p + kg : s1p + (kg - 512);
        } else {
            sa0 = a0 + kg; sa1 = a1 + kg;
        }
        if (!v) { sa0 = g.W; sa1 = g.W; }
        cp_async16(aD0 + buf, sa0, v ? 16 : 0);
        cp_async16(aD1 + buf, sa1, v ? 16 : 0);
        bool v0 = v && n0ok, v1 = v && n1ok;
        cp_async16(wD0 + buf, v0 ? (w0p + kg) : g.W, v0 ? 16 : 0);
        cp_async16(wD1 + buf, v1 ? (w1p + kg) : g.W, v1 ? 16 : 0);
    };

    #pragma unroll
    for (int p = 0; p < 3; p++) {
        if (p < nk) pf(p);
        cp_commit();
    }

    float c[2][4][4] = {};
    const int lr = lane & 15, lk = (lane >> 4) * 8;

    for (int i = 0; i < nk; i++) {
        if (i + 3 < nk) pf(i + 3);
        cp_commit();
        cp_wait<3>();
        __syncthreads();

        const uint32_t ab = asB + (i & 3) * STB;
        const uint32_t wb = wsB + (i & 3) * STB;

        #pragma unroll
        for (int kk = 0; kk < 32; kk += 16) {
            uint32_t a[2][4], bb[2][4];
            #pragma unroll
            for (int mt = 0; mt < 2; mt++)
                ldsm4(a[mt], ab + ((wm * 32 + mt * 16 + lr) * SK + kk + lk) * 2);
            #pragma unroll
            for (int n2 = 0; n2 < 2; n2++)
                ldsm4(bb[n2], wb + ((wn * 32 + n2 * 16 + lr) * SK + kk + lk) * 2);
            #pragma unroll
            for (int mt = 0; mt < 2; mt++)
                #pragma unroll
                for (int ns = 0; ns < 4; ns++) {
                    int n2 = ns >> 1, sel = ns & 1;
                    mma_f16(c[mt][ns], a[mt], bb[n2][sel], bb[n2][sel + 2]);
                }
        }
        __syncthreads();
    }

    const int gr = lane >> 2, gc = (lane & 3) * 2;
    #pragma unroll
    for (int mt = 0; mt < 2; mt++)
        #pragma unroll
        for (int ns = 0; ns < 4; ns++) {
            int row = mt0 + wm * 32 + mt * 16 + gr;
            int col = nt0 + wn * 32 + ns * 8 + gc;
            if (col < g.N) {
                if (OUTH) {
                    __half* Ch = (__half*)g.C;
                    Ch[(size_t)row * g.ldc + col]           = __float2half(c[mt][ns][0]);
                    Ch[(size_t)row * g.ldc + col + 1]       = __float2half(c[mt][ns][1]);
                    Ch[(size_t)(row + 8) * g.ldc + col]     = __float2half(c[mt][ns][2]);
                    Ch[(size_t)(row + 8) * g.ldc + col + 1] = __float2half(c[mt][ns][3]);
                } else {
                    g.C[(size_t)row * g.ldc + col]           = c[mt][ns][0];
                    g.C[(size_t)row * g.ldc + col + 1]       = c[mt][ns][1];
                    g.C[(size_t)(row + 8) * g.ldc + col]     = c[mt][ns][2];
                    g.C[(size_t)(row + 8) * g.ldc + col + 1] = c[mt][ns][3];
                }
            }
        }
}

__global__ __launch_bounds__(128) void k_g_plain(GH g)   { grun<MODE_PLAIN, false>(g); }
__global__ __launch_bounds__(128) void k_g_plain_h(GH g) { grun<MODE_PLAIN, true >(g); }
__global__ __launch_bounds__(128) void k_g_emb(GH g)     { grun<MODE_EMB,   false>(g); }
__global__ __launch_bounds__(128) void k_g_cs(GH g)      { grun<MODE_CS,    false>(g); }
__global__ __launch_bounds__(128) void k_g_plain_split(GH g) {
    int sp = blockIdx.z;
    g.kbeg = sp * g.K; g.kend = g.kbeg + g.K;
    g.C += (size_t)sp * BB * g.ldc;
    grun<MODE_PLAIN, false>(g);
}
__global__ __launch_bounds__(128) void k_gates(GH gi, GH gh) {
    int z = blockIdx.z;
    GH g = (z < 4) ? gi : gh;
    int sp = z & 3;
    g.kbeg = sp * g.K; g.kend = g.kbeg + g.K;
    g.C += (size_t)sp * BB * g.ldc;
    grun<MODE_PLAIN, false>(g);
}

// ---------------------------------------------------------------------------
// GRU: reduce split-K partials + precomputed emb part, then gate math
// ---------------------------------------------------------------------------
__global__ __launch_bounds__(256) void gru_kernel(
    const float* __restrict__ gip, const float* __restrict__ ghp,
    const float* __restrict__ giemb,
    const float* __restrict__ b_ih, const float* __restrict__ b_hh,
    const float* __restrict__ s_old,
    float* __restrict__ s_new, __half* __restrict__ s_h, int t)
{
    int idx = blockIdx.x * blockDim.x + threadIdx.x;   // BB*HD
    int b = idx >> 9, h = idx & 511;
    size_t ob = (size_t)b * 1536;
    size_t oe = ((size_t)t * BB + b) * 1536;

    float ir = giemb[oe + h]            + b_ih[h];
    float iz = giemb[oe + HD + h]       + b_ih[HD + h];
    float in = giemb[oe + 2 * HD + h]   + b_ih[2 * HD + h];
    float hr = b_hh[h], hz = b_hh[HD + h], hn = b_hh[2 * HD + h];
    #pragma unroll
    for (int z = 0; z < 4; z++) {
        size_t o = (size_t)z * BB * 1536 + ob;
        ir += gip[o + h];      iz += gip[o + HD + h];  in += gip[o + 2 * HD + h];
        hr += ghp[o + h];      hz += ghp[o + HD + h];  hn += ghp[o + 2 * HD + h];
    }
    float r = sigmoid_fast(ir + hr);
    float z = sigmoid_fast(iz + hz);
    float n = tanh_fast(in + r * hn);
    float so = s_old[idx];
    float sn = (1.0f - z) * n + z * so;
    s_new[idx] = sn;
    s_h[idx] = __float2half(sn);
}

// ---------------------------------------------------------------------------
// Fused attention (fp16 tables): q-reduce -> e -> softmax -> ctx -> p_copy
// ---------------------------------------------------------------------------
__global__ __launch_bounds__(512) void attn_kernel(
    const float* __restrict__ qp,      // [4][B][512] partials
    const float* __restrict__ att_b,
    const __half* __restrict__ proj,   // [B,L,A] fp16
    const __half* __restrict__ ench,   // [B,L,HE] fp16
    const float* __restrict__ vvec,
    const int*   __restrict__ src,
    const float* __restrict__ s_new,
    const float* __restrict__ copy_W,
    const float* __restrict__ copy_b,
    float* __restrict__ attn_out,
    __half* __restrict__ ctx_h,
    float* __restrict__ pc_out)
{
    __shared__ __align__(16) float es[LL];
    __shared__ float part[2][HE];
    __shared__ float red[32];

    int b = blockIdx.x, tid = threadIdx.x;
    int warp = tid >> 5, lane = tid & 31;

    float qf[2][8], vf[2][8];
    #pragma unroll
    for (int j = 0; j < 2; j++) {
        int base = (lane + 32 * j) * 8;
        float4 b0 = *(const float4*)(att_b + base);
        float4 b1 = *(const float4*)(att_b + base + 4);
        qf[j][0] = b0.x; qf[j][1] = b0.y; qf[j][2] = b0.z; qf[j][3] = b0.w;
        qf[j][4] = b1.x; qf[j][5] = b1.y; qf[j][6] = b1.z; qf[j][7] = b1.w;
        #pragma unroll
        for (int z = 0; z < 4; z++) {
            const float* qz = qp + ((size_t)z * BB + b) * 512 + base;
            float4 q0 = *(const float4*)qz;
            float4 q1 = *(const float4*)(qz + 4);
            qf[j][0] += q0.x; qf[j][1] += q0.y; qf[j][2] += q0.z; qf[j][3] += q0.w;
            qf[j][4] += q1.x; qf[j][5] += q1.y; qf[j][6] += q1.z; qf[j][7] += q1.w;
        }
        float4 v0 = *(const float4*)(vvec + base);
        float4 v1 = *(const float4*)(vvec + base + 4);
        vf[j][0] = v0.x; vf[j][1] = v0.y; vf[j][2] = v0.z; vf[j][3] = v0.w;
        vf[j][4] = v1.x; vf[j][5] = v1.y; vf[j][6] = v1.z; vf[j][7] = v1.w;
    }

    // Phase 1: scores
    for (int l = warp; l < LL; l += 16) {
        const uint4* pp = (const uint4*)(proj + ((size_t)b * LL + l) * AA);
        float acc = 0.0f;
        #pragma unroll
        for (int j = 0; j < 2; j++) {
            uint4 pv = pp[lane + 32 * j];
            const __half2* h2 = (const __half2*)&pv;
            #pragma unroll
            for (int p = 0; p < 4; p++) {
                float2 f = __half22float2(h2[p]);
                acc += tanhA(f.x + qf[j][2 * p])     * vf[j][2 * p];
                acc += tanhA(f.y + qf[j][2 * p + 1]) * vf[j][2 * p + 1];
            }
        }
        acc = warpSum(acc);
        if (lane == 0)
            es[l] = (src[b * LL + l] == PAD_ID) ? -1e30f : acc;
    }
    __syncthreads();

    // Phase 2: softmax over L
    float ev = (tid < LL) ? es[tid] : -INFINITY;
    float m  = blockMax(ev, red);
    float p  = (tid < LL) ? __expf(ev - m) : 0.0f;
    float Z  = blockSum(p, red);
    float a  = p / Z;
    if (tid < LL) { es[tid] = a; attn_out[b * LL + tid] = a; }
    __syncthreads();

    // Phase 3: ctx via fp16 enc, 2 L-groups x 256 column-pairs
    int gg = tid >> 8, cc = tid & 255;
    const __half2* eb = (const __half2*)(ench + (size_t)b * LL * HE) + cc;
    float ax = 0.0f, ay = 0.0f;
    int l0 = gg * 200;
    #pragma unroll 4
    for (int l = l0; l < l0 + 200; l++) {
        float2 f = __half22float2(eb[(size_t)l * 256]);
        ax += es[l] * f.x;
        ay += es[l] * f.y;
    }
    part[gg][2 * cc]     = ax;
    part[gg][2 * cc + 1] = ay;
    __syncthreads();

    float ctxv = part[0][tid] + part[1][tid];
    ctx_h[b * HE + tid] = __float2half(ctxv);

    // Phase 4: p_copy
    float pp_ = s_new[b * HD + tid] * copy_W[tid] + ctxv * copy_W[HD + tid];
    float tot = blockSum(pp_, red);
    if (tid == 0) pc_out[b] = sigmoid_fast(tot + copy_b[0]);
}

// ---------------------------------------------------------------------------
// Batched tail kernels (operate on a chunk of steps)
// ---------------------------------------------------------------------------
__global__ __launch_bounds__(256) void mred_all(
    const float* __restrict__ rv, const float* __restrict__ rvemb,
    const float* __restrict__ read_b, __half* __restrict__ mh)
{
    int idx = blockIdx.x * 256 + threadIdx.x;     // rows*256
    int row = idx >> 8, c = idx & 255;
    size_t o = (size_t)row * 512;
    float r0 = rv[o + 2 * c]     + rvemb[o + 2 * c]     + read_b[2 * c];
    float r1 = rv[o + 2 * c + 1] + rvemb[o + 2 * c + 1] + read_b[2 * c + 1];
    mh[idx] = __float2half(fmaxf(r0, r1));
}

__global__ __launch_bounds__(1024) void output_all(
    const float* __restrict__ energy,   // indexed by global row
    const float* __restrict__ attnb,
    const float* __restrict__ pcb,
    float* __restrict__ out, int row0)
{
    __shared__ float red[32];
    int row = row0 + blockIdx.x;          // t*128 + b
    int t = row >> 7, b = row & 127;
    int tid = threadIdx.x;
    const float4* eb4 = (const float4*)(energy + (size_t)row * VV);

    float mx = -INFINITY;
    for (int j = tid; j < VV / 4; j += 1024) {
        float4 v = eb4[j];
        mx = fmaxf(mx, fmaxf(fmaxf(v.x, v.y), fmaxf(v.z, v.w)));
    }
    mx = blockMax(mx, red);

    float sm = 0.0f;
    for (int j = tid; j < VV / 4; j += 1024) {
        float4 v = eb4[j];
        sm += __expf(v.x - mx) + __expf(v.y - mx) + __expf(v.z - mx) + __expf(v.w - mx);
    }
    sm = blockSum(sm, red);

    float pc = pcb[row];
    float scale = (1.0f - pc) / sm;
    float* ob = out + ((size_t)b * TT + t) * (VV + LL);
    float4* ob4 = (float4*)ob;
    for (int j = tid; j < VV / 4; j += 1024) {
        float4 v = eb4[j], o;
        o.x = __logf(__expf(v.x - mx) * scale + 1e-12f);
        o.y = __logf(__expf(v.y - mx) * scale + 1e-12f);
        o.z = __logf(__expf(v.z - mx) * scale + 1e-12f);
        o.w = __logf(__expf(v.w - mx) * scale + 1e-12f);
        ob4[j] = o;
    }
    const float4* at4 = (const float4*)(attnb + (size_t)row * LL);
    float4* oc4 = (float4*)(ob + VV);
    for (int j = tid; j < LL / 4; j += 1024) {
        float4 a = at4[j], o;
        o.x = __logf(fmaf(pc, a.x, 1e-12f));
        o.y = __logf(fmaf(pc, a.y, 1e-12f));
        o.z = __logf(fmaf(pc, a.z, 1e-12f));
        o.w = __logf(fmaf(pc, a.w, 1e-12f));
        oc4[j] = o;
    }
}

// ---------------------------------------------------------------------------
// Host orchestration: critical chain on stream 0, chunked batched tail on side
// ---------------------------------------------------------------------------
static inline void cvt(const float* s, __half* d, int rows, int sstr, int soff,
                       int dstr, int clen) {
    int total = rows * dstr;
    int grid = (total + 255) / 256;
    if (grid > 8192) grid = 8192;
    cvt_pad<<<grid, 256>>>(s, d, rows, sstr, soff, dstr, clen);
}

extern "C" void kernel_launch(void* const* d_in, const int* in_sizes, int n_in,
                              void* d_out, int out_size)
{
    const float* enc     = (const float*)d_in[0];
    const float* s_in    = (const float*)d_in[1];
    const int*   src     = (const int*)  d_in[2];
    const int*   tgt     = (const int*)  d_in[3];
    const float* embed   = (const float*)d_in[4];
    const float* W_ih    = (const float*)d_in[5];
    const float* b_ih    = (const float*)d_in[6];
    const float* W_hh    = (const float*)d_in[7];
    const float* b_hh    = (const float*)d_in[8];
    const float* att_Wh  = (const float*)d_in[9];
    const float* att_Ws  = (const float*)d_in[10];
    const float* att_b   = (const float*)d_in[11];
    const float* att_v   = (const float*)d_in[12];
    const float* copy_W  = (const float*)d_in[13];
    const float* copy_b  = (const float*)d_in[14];
    const float* read_W  = (const float*)d_in[15];
    const float* read_b  = (const float*)d_in[16];
    const float* read_Wo = (const float*)d_in[17];
    float* out = (float*)d_out;

    __half *p_ench, *p_projh, *p_embh, *p_Wihe, *p_Wihc, *p_Whh, *p_Ws, *p_Wh;
    __half *p_Wre, *p_Wrc, *p_Wo, *p_shh, *p_chh, *p_mh;
    float *p_giemb, *p_rvemb, *p_gip, *p_ghp, *p_qp, *p_rv;
    float *p_sf, *p_attn, *p_pc, *p_energy;

    cudaGetSymbolAddress((void**)&p_ench,  g_enc_h);
    cudaGetSymbolAddress((void**)&p_projh, g_proj_h);
    cudaGetSymbolAddress((void**)&p_embh,  g_embed_h);
    cudaGetSymbolAddress((void**)&p_Wihe,  g_Wih_e);
    cudaGetSymbolAddress((void**)&p_Wihc,  g_Wih_c);
    cudaGetSymbolAddress((void**)&p_Whh,   g_Whh);
    cudaGetSymbolAddress((void**)&p_Ws,    g_Ws);
    cudaGetSymbolAddress((void**)&p_Wh,    g_Wh);
    cudaGetSymbolAddress((void**)&p_Wre,   g_Wr_e);
    cudaGetSymbolAddress((void**)&p_Wrc,   g_Wr_c);
    cudaGetSymbolAddress((void**)&p_Wo,    g_Wo);
    cudaGetSymbolAddress((void**)&p_giemb, g_giemb);
    cudaGetSymbolAddress((void**)&p_rvemb, g_rvemb);
    cudaGetSymbolAddress((void**)&p_gip,   g_gi_p);
    cudaGetSymbolAddress((void**)&p_ghp,   g_gh_p);
    cudaGetSymbolAddress((void**)&p_qp,    g_qp);
    cudaGetSymbolAddress((void**)&p_sf,    g_sf);
    cudaGetSymbolAddress((void**)&p_shh,   g_shh);
    cudaGetSymbolAddress((void**)&p_chh,   g_chh);
    cudaGetSymbolAddress((void**)&p_attn,  g_attnb);
    cudaGetSymbolAddress((void**)&p_pc,    g_pcb);
    cudaGetSymbolAddress((void**)&p_rv,    g_rv_all);
    cudaGetSymbolAddress((void**)&p_mh,    g_mh_all);
    cudaGetSymbolAddress((void**)&p_energy,g_energy_all);

    // Side stream + events (3 chunk forks + 1 join)
    cudaStream_t side;
    cudaStreamCreateWithFlags(&side, cudaStreamNonBlocking);
    cudaEvent_t evF[TT / CHUNK], evJ;
    for (int c = 0; c < TT / CHUNK; c++)
        cudaEventCreateWithFlags(&evF[c], cudaEventDisableTiming);
    cudaEventCreateWithFlags(&evJ, cudaEventDisableTiming);

    // ---- Precompute: conversions / repacks (stream 0) ----
    cvt(enc,     p_ench, BB * LL, HE, 0, HE, HE);
    cvt(embed,   p_embh, VV, EE, 0, 304, EE);
    cvt(W_ih,    p_Wihe, 1536, 812, 0, 304, 300);
    cvt(W_ih,    p_Wihc, 1536, 812, 300, 512, 512);
    cvt(W_hh,    p_Whh,  1536, 512, 0, 512, 512);
    cvt(att_Ws,  p_Ws,   512, 512, 0, 512, 512);
    cvt(att_Wh,  p_Wh,   512, 512, 0, 512, 512);
    cvt(read_W,  p_Wre,  512, 1324, 0, 304, 300);
    cvt(read_W,  p_Wrc,  512, 1324, 300, 1024, 1024);
    cvt(read_Wo, p_Wo,   VV, 256, 0, 256, 256);
    cvt(s_in,    p_shh,  BB, HD, 0, HD, HD);     // s ring slot 0

    cudaMemcpyAsync(p_sf, s_in, BB * HD * sizeof(float),
                    cudaMemcpyDeviceToDevice, 0);
    cudaMemsetAsync(p_chh, 0, BB * HE * sizeof(__half), 0);   // ctx slot 0

    // ---- Precompute: big GEMMs ----
    {   // proj = enc @ att_Wh^T -> fp16
        GH g{}; g.A = p_ench; g.lda = HE; g.W = p_Wh; g.ldw = 512;
        g.C = (float*)p_projh; g.ldc = AA; g.N = AA;
        g.kbeg = 0; g.kend = 512;
        k_g_plain_h<<<dim3(8, 800), 128, SMEM_GEMM>>>(g);
    }
    {   // giemb[all t] = emb @ Wih_e^T
        GH g{}; g.embed = p_embh; g.tgt = tgt; g.W = p_Wihe; g.ldw = 304;
        g.C = p_giemb; g.ldc = 1536; g.N = 1536;
        g.kbeg = 0; g.kend = 304;
        k_g_emb<<<dim3(24, 60), 128, SMEM_GEMM>>>(g);
    }
    {   // rvemb[all t] = emb @ Wr_e^T
        GH g{}; g.embed = p_embh; g.tgt = tgt; g.W = p_Wre; g.ldw = 304;
        g.C = p_rvemb; g.ldc = 512; g.N = 512;
        g.kbeg = 0; g.kend = 304;
        k_g_emb<<<dim3(8, 60), 128, SMEM_GEMM>>>(g);
    }

    for (int t = 0; t < TT; t++) {
        // Per-step ring slots
        float*  sCur = p_sf  + (size_t)t * BB * HD;
        float*  sNxt = p_sf  + (size_t)(t + 1) * BB * HD;
        __half* shC  = p_shh + (size_t)t * BB * HD;
        __half* shN  = p_shh + (size_t)(t + 1) * BB * HD;
        __half* chC  = p_chh + (size_t)t * BB * HE;
        __half* chN  = p_chh + (size_t)(t + 1) * BB * HE;
        float*  atT  = p_attn + (size_t)t * BB * LL;
        float*  pcT  = p_pc + (size_t)t * BB;

        // ---- Critical chain (stream 0): 4 nodes ----
        {   // gi_ctx (splitK4) + gh (splitK4), fused launch
            GH gi{}; gi.A = chC; gi.lda = 512; gi.W = p_Wihc; gi.ldw = 512;
            gi.C = p_gip; gi.ldc = 1536; gi.N = 1536; gi.K = 128;
            GH gh{}; gh.A = shC; gh.lda = 512; gh.W = p_Whh; gh.ldw = 512;
            gh.C = p_ghp; gh.ldc = 1536; gh.N = 1536; gh.K = 128;
            k_gates<<<dim3(24, 2, 8), 128, SMEM_GEMM>>>(gi, gh);
        }
        gru_kernel<<<(BB * HD) / 256, 256>>>(p_gip, p_ghp, p_giemb,
                                             b_ih, b_hh, sCur, sNxt, shN, t);
        {   // q partials = s_new @ att_Ws^T (splitK4)
            GH g{}; g.A = shN; g.lda = 512; g.W = p_Ws; g.ldw = 512;
            g.C = p_qp; g.ldc = 512; g.N = 512; g.K = 128;
            k_g_plain_split<<<dim3(8, 2, 4), 128, SMEM_GEMM>>>(g);
        }
        attn_kernel<<<BB, 512>>>(p_qp, att_b, p_projh, p_ench, att_v, src,
                                 sNxt, copy_W, copy_b, atT, chN, pcT);

        // ---- End of chunk? fork batched tail for steps [t-CHUNK+1, t] ----
        if ((t + 1) % CHUNK == 0) {
            int c = t / CHUNK;
            int t0 = c * CHUNK;                 // first step of chunk
            int rows = CHUNK * BB;              // 1280
            cudaEventRecord(evF[c], 0);
            cudaStreamWaitEvent(side, evF[c], 0);

            {   // rv = [ctx(t+1), s(t+1)] @ Wr_c^T for the chunk
                GH g{}; g.ctx = p_chh + (size_t)(t0 + 1) * BB * HE;
                g.s = p_shh + (size_t)(t0 + 1) * BB * HD;
                g.W = p_Wrc; g.ldw = 1024;
                g.C = p_rv + (size_t)t0 * BB * 512; g.ldc = 512; g.N = 512;
                g.kbeg = 0; g.kend = 1024;
                k_g_cs<<<dim3(8, rows / 64), 128, SMEM_GEMM, side>>>(g);
            }
            mred_all<<<rows, 256, 0, side>>>(
                p_rv + (size_t)t0 * BB * 512,
                p_rvemb + (size_t)t0 * BB * 512,
                read_b, p_mh + (size_t)t0 * BB * 256);
            {   // energy = m @ read_Wo^T for the chunk
                GH g{}; g.A = p_mh + (size_t)t0 * BB * 256; g.lda = 256;
                g.W = p_Wo; g.ldw = 256;
                g.C = p_energy + (size_t)t0 * BB * VV; g.ldc = VV; g.N = VV;
                g.kbeg = 0; g.kend = 256;
                k_g_plain<<<dim3(313, rows / 64), 128, SMEM_GEMM, side>>>(g);
            }
            output_all<<<rows, 1024, 0, side>>>(p_energy, p_attn, p_pc, out,
                                                t0 * BB);
        }
    }

    // ---- Join side stream back before returning ----
    cudaEventRecord(evJ, side);
    cudaStreamWaitEvent(0, evJ, 0);
}